// round 6
// baseline (speedup 1.0000x reference)
#include <cuda_runtime.h>
#include <cuda_bf16.h>

// B=8, C=16, H=512, W=512, M=N=15 -> P=Q=16, BC=128
// basis: [H*W,16,16] f32 (separable Bernstein products), K: [128,16,16] f32
// out: [128,512,512] f32
#define Hh 512
#define Ww 512
#define BC 128
#define Pp 16
#define Qq 16
#define HT 64

__device__ float g_Bu[Hh * Pp];     // 32 KB  Bu[h][p]
__device__ float g_BvT[Qq * Ww];    // 32 KB  BvT[q][w]  (transposed!)

// ---- f32x2 packed helpers (Blackwell) ------------------------------------
__device__ __forceinline__ unsigned long long pack_f32x2(float x, float y) {
    unsigned long long r;
    asm("mov.b64 %0, {%1, %2};" : "=l"(r) : "f"(x), "f"(y));
    return r;
}
__device__ __forceinline__ void unpack_f32x2(unsigned long long v, float& x, float& y) {
    asm("mov.b64 {%0, %1}, %2;" : "=f"(x), "=f"(y) : "l"(v));
}
__device__ __forceinline__ unsigned long long fma_f32x2(
    unsigned long long a, unsigned long long b, unsigned long long c) {
    unsigned long long d;
    asm("fma.rn.f32x2 %0, %1, %2, %3;" : "=l"(d) : "l"(a), "l"(b), "l"(c));
    return d;
}
__device__ __forceinline__ unsigned long long splat64(float x) {
    unsigned int b = __float_as_uint(x);
    return ((unsigned long long)b << 32) | b;
}

// -------------------------------------------------------------------------
// Stage 1: recover separable factors (Bernstein partition of unity):
//   Bu[h,p]  = sum_q basis[h*W + 0, p, q]
//   BvT[q,w] = sum_p basis[0*W + w, p, q]
// -------------------------------------------------------------------------
__global__ void bez_extract_kernel(const float* __restrict__ basis) {
    int idx = blockIdx.x * blockDim.x + threadIdx.x;
    if (idx < Hh * Pp) {
        int h = idx >> 4;
        int p = idx & 15;
        const float4* r =
            reinterpret_cast<const float4*>(basis + (size_t)h * Ww * 256 + p * 16);
        float4 a = r[0], b = r[1], c = r[2], d = r[3];
        g_Bu[idx] = ((a.x + a.y) + (a.z + a.w)) + ((b.x + b.y) + (b.z + b.w)) +
                    ((c.x + c.y) + (c.z + c.w)) + ((d.x + d.y) + (d.z + d.w));
    } else if (idx < Hh * Pp + Ww * Qq) {
        int j = idx - Hh * Pp;
        int w = j >> 4;
        int q = j & 15;
        const float* row = basis + (size_t)w * 256 + q;
        float s = 0.f;
#pragma unroll
        for (int p = 0; p < 16; ++p) s += row[p * 16];
        g_BvT[q * Ww + w] = s;      // transposed layout
    }
}

// -------------------------------------------------------------------------
// Fused stage 2+3: out[bc, h, w] = sum_p Bu[h,p] * (sum_q K[bc,p,q]*Bv[w,q])
// Thread t owns float4 column w=4t. Prologue builds T[p, w0..w3] in
// registers (16 float4 loads of BvT + 512 FFMA2 with K broadcast from
// smem). Main loop: 32 FFMA2 + float4 streaming store per h-row.
// -------------------------------------------------------------------------
__global__ __launch_bounds__(128) void bez_main_kernel(
    const float* __restrict__ Kmat, float* __restrict__ out) {
    const int bc  = blockIdx.y;
    const int h0  = blockIdx.x * HT;
    const int tid = threadIdx.x;          // 0..127

    __shared__ unsigned long long sK2[Pp * Qq];    // 2 KB  K[bc] splatted
    __shared__ unsigned long long sBu2[HT * Pp];   // 8 KB  Bu tile splatted

    sK2[tid]       = splat64(Kmat[bc * 256 + tid]);
    sK2[tid + 128] = splat64(Kmat[bc * 256 + tid + 128]);
    for (int i = tid; i < HT * Pp; i += 128)
        sBu2[i] = splat64(g_Bu[h0 * Pp + i]);
    __syncthreads();

    // Prologue: T[p, 4t..4t+3] = sum_q K[p,q] * BvT[q, 4t..4t+3]
    unsigned long long tlo[Pp], thi[Pp];
#pragma unroll
    for (int p = 0; p < Pp; ++p) { tlo[p] = 0ull; thi[p] = 0ull; }

    const float4* __restrict__ bvt = reinterpret_cast<const float4*>(g_BvT);
#pragma unroll
    for (int q = 0; q < Qq; ++q) {
        float4 bv = bvt[q * (Ww / 4) + tid];
        const unsigned long long blo = pack_f32x2(bv.x, bv.y);
        const unsigned long long bhi = pack_f32x2(bv.z, bv.w);
#pragma unroll
        for (int p = 0; p < Pp; ++p) {
            const unsigned long long k = sK2[p * Qq + q];   // LDS broadcast
            tlo[p] = fma_f32x2(k, blo, tlo[p]);
            thi[p] = fma_f32x2(k, bhi, thi[p]);
        }
    }

    // Main loop: 64 output rows.
    float4* __restrict__ o =
        reinterpret_cast<float4*>(out + ((size_t)bc * Hh + h0) * Ww);
#pragma unroll 2
    for (int hh = 0; hh < HT; ++hh) {
        unsigned long long alo = 0ull, ahi = 0ull;
#pragma unroll
        for (int p = 0; p < Pp; ++p) {
            const unsigned long long b = sBu2[hh * Pp + p];
            alo = fma_f32x2(b, tlo[p], alo);
            ahi = fma_f32x2(b, thi[p], ahi);
        }
        float4 r;
        unpack_f32x2(alo, r.x, r.y);
        unpack_f32x2(ahi, r.z, r.w);
        __stcs(&o[hh * (Ww / 4) + tid], r);
    }
}

// -------------------------------------------------------------------------
extern "C" void kernel_launch(void* const* d_in, const int* in_sizes, int n_in,
                              void* d_out, int out_size) {
    const float* Kmat  = nullptr;
    const float* basis = nullptr;
    for (int i = 0; i < n_in; ++i) {
        if (in_sizes[i] == BC * Pp * Qq)            Kmat  = (const float*)d_in[i];
        else if (in_sizes[i] == Hh * Ww * Pp * Qq)  basis = (const float*)d_in[i];
    }
    float* out = (float*)d_out;

    bez_extract_kernel<<<128, 128>>>(basis);
    dim3 grid(Hh / HT, BC);
    bez_main_kernel<<<grid, 128>>>(Kmat, out);
}

// round 8
// speedup vs baseline: 1.0008x; 1.0008x over previous
#include <cuda_runtime.h>
#include <cuda_bf16.h>

// B=8, C=16, H=512, W=512, M=N=15 -> P=Q=16, BC=128
#define Hh 512
#define Ww 512
#define BC 128
#define Pp 16
#define Qq 16
#define HT 64

__device__ float g_Bu[Hh * Pp];       // 32 KB  Bu[h][p]
__device__ float g_Bv[Ww * Qq];       // 32 KB  Bv[w][q]
__device__ float g_T[BC * Pp * Ww];   //  4 MB  T[bc][p][w]

// ---- f32x2 packed helpers (Blackwell) ------------------------------------
__device__ __forceinline__ unsigned long long pack_f32x2(float x, float y) {
    unsigned long long r;
    asm("mov.b64 %0, {%1, %2};" : "=l"(r) : "f"(x), "f"(y));
    return r;
}
__device__ __forceinline__ void unpack_f32x2(unsigned long long v, float& x, float& y) {
    asm("mov.b64 {%0, %1}, %2;" : "=f"(x), "=f"(y) : "l"(v));
}
__device__ __forceinline__ unsigned long long fma_f32x2(
    unsigned long long a, unsigned long long b, unsigned long long c) {
    unsigned long long d;
    asm("fma.rn.f32x2 %0, %1, %2, %3;" : "=l"(d) : "l"(a), "l"(b), "l"(c));
    return d;
}
__device__ __forceinline__ unsigned long long splat64(float x) {
    unsigned int b = __float_as_uint(x);
    return ((unsigned long long)b << 32) | b;
}

// -------------------------------------------------------------------------
// Stage 1: recover separable factors (Bernstein partition of unity):
//   Bu[h,p] = sum_q basis[h*W + 0, p, q]
//   Bv[w,q] = sum_p basis[0*W + w, p, q]
// -------------------------------------------------------------------------
__global__ void bez_extract_kernel(const float* __restrict__ basis) {
    int idx = blockIdx.x * blockDim.x + threadIdx.x;
    if (idx < Hh * Pp) {
        int h = idx >> 4;
        int p = idx & 15;
        const float4* r =
            reinterpret_cast<const float4*>(basis + (size_t)h * Ww * 256 + p * 16);
        float4 a = r[0], b = r[1], c = r[2], d = r[3];
        g_Bu[idx] = ((a.x + a.y) + (a.z + a.w)) + ((b.x + b.y) + (b.z + b.w)) +
                    ((c.x + c.y) + (c.z + c.w)) + ((d.x + d.y) + (d.z + d.w));
    } else if (idx < Hh * Pp + Ww * Qq) {
        int j = idx - Hh * Pp;
        int w = j >> 4;
        int q = j & 15;
        const float* row = basis + (size_t)w * 256 + q;
        float s = 0.f;
#pragma unroll
        for (int p = 0; p < 16; ++p) s += row[p * 16];
        g_Bv[j] = s;
    }
}

// -------------------------------------------------------------------------
// Stage 2: T[bc, p, w] = sum_q Bv[w,q] * K[bc, p, q]
// -------------------------------------------------------------------------
__global__ void bez_stage2_kernel(const float* __restrict__ Kmat) {
    __shared__ float sK[Pp * Qq];
    const int bc  = blockIdx.x;
    const int tid = threadIdx.x;          // 256
    sK[tid] = Kmat[bc * 256 + tid];
    __syncthreads();

    for (int w = tid; w < Ww; w += 256) {
        float bv[Qq];
#pragma unroll
        for (int q = 0; q < Qq; ++q) bv[q] = g_Bv[w * Qq + q];
#pragma unroll
        for (int p = 0; p < Pp; ++p) {
            float s = 0.f;
#pragma unroll
            for (int q = 0; q < Qq; ++q) s += bv[q] * sK[p * Qq + q];
            g_T[((size_t)bc * Pp + p) * Ww + w] = s;
        }
    }
}

// -------------------------------------------------------------------------
// Stage 3: out[bc, h, w] = sum_p Bu[h,p] * T[bc, p, w]
// Thread t owns float4 column w=4t (T register-resident as f32x2 pairs).
// Bu tile in smem as splatted 64-bit words; read as ulonglong2 (LDS.128
// broadcast, 2 p-values per load -> 8 LDS/row). Two rows per iteration
// give 4 independent FMA chains for latency coverage at low occupancy.
// -------------------------------------------------------------------------
__global__ __launch_bounds__(128) void bez_stage3_kernel(float* __restrict__ out) {
    const int bc  = blockIdx.y;
    const int h0  = blockIdx.x * HT;
    const int tid = threadIdx.x;          // 0..127

    __shared__ unsigned long long sBu2[HT * Pp];   // 8 KB, splatted

    unsigned long long tlo[Pp], thi[Pp];
    const float4* __restrict__ Tp =
        reinterpret_cast<const float4*>(g_T + (size_t)bc * Pp * Ww);
#pragma unroll
    for (int p = 0; p < Pp; ++p) {
        float4 v = Tp[p * (Ww / 4) + tid];
        tlo[p] = pack_f32x2(v.x, v.y);
        thi[p] = pack_f32x2(v.z, v.w);
    }
    for (int i = tid; i < HT * Pp; i += 128)
        sBu2[i] = splat64(g_Bu[h0 * Pp + i]);
    __syncthreads();

    const ulonglong2* __restrict__ sBuV =
        reinterpret_cast<const ulonglong2*>(sBu2);   // [hh][p/2]

    float4* __restrict__ o =
        reinterpret_cast<float4*>(out + ((size_t)bc * Hh + h0) * Ww);
    for (int hh = 0; hh < HT; hh += 2) {
        unsigned long long a0l = 0ull, a0h = 0ull, a1l = 0ull, a1h = 0ull;
#pragma unroll
        for (int k = 0; k < Pp / 2; ++k) {
            const ulonglong2 b0 = sBuV[hh * 8 + k];
            const ulonglong2 b1 = sBuV[(hh + 1) * 8 + k];
            a0l = fma_f32x2(b0.x, tlo[2 * k], a0l);
            a0h = fma_f32x2(b0.x, thi[2 * k], a0h);
            a1l = fma_f32x2(b1.x, tlo[2 * k], a1l);
            a1h = fma_f32x2(b1.x, thi[2 * k], a1h);
            a0l = fma_f32x2(b0.y, tlo[2 * k + 1], a0l);
            a0h = fma_f32x2(b0.y, thi[2 * k + 1], a0h);
            a1l = fma_f32x2(b1.y, tlo[2 * k + 1], a1l);
            a1h = fma_f32x2(b1.y, thi[2 * k + 1], a1h);
        }
        float4 r0, r1;
        unpack_f32x2(a0l, r0.x, r0.y);
        unpack_f32x2(a0h, r0.z, r0.w);
        unpack_f32x2(a1l, r1.x, r1.y);
        unpack_f32x2(a1h, r1.z, r1.w);
        __stcs(&o[hh * (Ww / 4) + tid], r0);
        __stcs(&o[(hh + 1) * (Ww / 4) + tid], r1);
    }
}

// -------------------------------------------------------------------------
extern "C" void kernel_launch(void* const* d_in, const int* in_sizes, int n_in,
                              void* d_out, int out_size) {
    const float* Kmat  = nullptr;
    const float* basis = nullptr;
    for (int i = 0; i < n_in; ++i) {
        if (in_sizes[i] == BC * Pp * Qq)            Kmat  = (const float*)d_in[i];
        else if (in_sizes[i] == Hh * Ww * Pp * Qq)  basis = (const float*)d_in[i];
    }
    float* out = (float*)d_out;

    bez_extract_kernel<<<128, 128>>>(basis);
    bez_stage2_kernel<<<BC, 256>>>(Kmat);
    dim3 grid3(Hh / HT, BC);
    bez_stage3_kernel<<<grid3, 128>>>(out);
}